// round 1
// baseline (speedup 1.0000x reference)
#include <cuda_runtime.h>
#include <cstddef>

#define U_N 50000
#define I_N 100000
#define E_N 1600000
#define B_N 16384

// ---------------- scratch layout (float offsets) ----------------
// work buffer (never zeroed)
constexpr size_t UH1 = 0;              // U*64
constexpr size_t IH1 = 3200000;        // I*64
constexpr size_t SU1 = 9600000;        // U*8
constexpr size_t SI1 = 10000000;       // I*8
constexpr size_t HUo = 10800000;       // U*64
constexpr size_t HIo = 14000000;       // I*64
constexpr size_t UH2 = 20400000;       // U*64
constexpr size_t IH2 = 23600000;       // I*64
constexpr size_t SU2 = 30000000;       // U (padded)
constexpr size_t SI2 = 30050048;       // I (padded)
constexpr size_t WORK_FLOATS = 30150080;

// accumulator buffer (zeroed every launch via one memset)
constexpr size_t AGGI1 = 0;            // U*64
constexpr size_t RS1   = 3200000;      // U*8
constexpr size_t AGGU1 = 3600000;      // I*64
constexpr size_t CS1   = 10000000;     // I*8
constexpr size_t AGGI2 = 10800000;     // U*64
constexpr size_t RS2   = 14000000;     // U (padded)
constexpr size_t AGGU2 = 14050048;     // I*64
constexpr size_t CS2   = 20450048;     // I (padded)
constexpr size_t ACC_FLOATS = 20550080;

__device__ __align__(16) float g_work[WORK_FLOATS];
__device__ __align__(16) float g_acc[ACC_FLOATS];

// ---------------- helpers ----------------
__device__ __forceinline__ void red4(float* p, float a, float b, float c, float d) {
    asm volatile("red.global.add.v4.f32 [%0], {%1,%2,%3,%4};"
                 :: "l"(p), "f"(a), "f"(b), "f"(c), "f"(d) : "memory");
}

__device__ __forceinline__ float elu1(float x) {
    return x > 0.f ? x : expm1f(x);
}

// ---------------- layer-1 GEMM + per-head scores ----------------
// Y[r][h*8+j] = sum_d X[r][d] * W[h][d][j];  S[r][h] = sum_j Y[r][h*8+j]*a[h*16+aoff+j]
__global__ void gemm_l1(const float* __restrict__ X,
                        const float* __restrict__ W,   // [8][64][8]
                        const float* __restrict__ a,   // [8][16]
                        int aoff,
                        float* __restrict__ Y, float* __restrict__ S)
{
    __shared__ float Ws[64 * 64];
    __shared__ float Es[16 * 64];
    int tid = threadIdx.x;
#pragma unroll
    for (int k = 0; k < 16; k++) {
        int idx = tid + k * 256;
        int d = idx >> 6, c = idx & 63;
        Ws[idx] = W[(c >> 3) * 512 + d * 8 + (c & 7)];
    }
    size_t r0 = (size_t)blockIdx.x * 16;
    ((float4*)Es)[tid] = ((const float4*)(X + r0 * 64))[tid];
    __syncthreads();

    int q = tid & 15;
    int tr = tid >> 4;
    float4 acc = make_float4(0.f, 0.f, 0.f, 0.f);
    const float4* Ws4 = (const float4*)Ws;
#pragma unroll
    for (int d = 0; d < 64; d++) {
        float e = Es[tr * 64 + d];
        float4 w = Ws4[d * 16 + q];
        acc.x += e * w.x; acc.y += e * w.y; acc.z += e * w.z; acc.w += e * w.w;
    }
    size_t r = r0 + tr;
    ((float4*)Y)[r * 16 + q] = acc;
    int h = q >> 1;
    const float* ap = a + h * 16 + aoff + (q & 1) * 4;
    float p = acc.x * ap[0] + acc.y * ap[1] + acc.z * ap[2] + acc.w * ap[3];
    p += __shfl_xor_sync(0xffffffffu, p, 1);
    if ((q & 1) == 0) S[r * 8 + h] = p;
}

// ---------------- layer-2 GEMM + scalar score ----------------
// Y[r][d] = sum_k X[r][k]*W[k*64+d];  S[r] = sum_d Y[r][d]*a[aoff+d]
__global__ void gemm_l2(const float* __restrict__ X,
                        const float* __restrict__ W,   // [64][64]
                        const float* __restrict__ a,   // [128]
                        int aoff,
                        float* __restrict__ Y, float* __restrict__ S)
{
    __shared__ float Ws[64 * 64];
    __shared__ float Es[16 * 64];
    int tid = threadIdx.x;
#pragma unroll
    for (int k = 0; k < 4; k++)
        ((float4*)Ws)[tid + k * 256] = ((const float4*)W)[tid + k * 256];
    size_t r0 = (size_t)blockIdx.x * 16;
    ((float4*)Es)[tid] = ((const float4*)(X + r0 * 64))[tid];
    __syncthreads();

    int q = tid & 15;
    int tr = tid >> 4;
    float4 acc = make_float4(0.f, 0.f, 0.f, 0.f);
    const float4* Ws4 = (const float4*)Ws;
#pragma unroll
    for (int k = 0; k < 64; k++) {
        float e = Es[tr * 64 + k];
        float4 w = Ws4[k * 16 + q];
        acc.x += e * w.x; acc.y += e * w.y; acc.z += e * w.z; acc.w += e * w.w;
    }
    size_t r = r0 + tr;
    ((float4*)Y)[r * 16 + q] = acc;
    const float* ap = a + aoff + q * 4;
    float p = acc.x * ap[0] + acc.y * ap[1] + acc.z * ap[2] + acc.w * ap[3];
#pragma unroll
    for (int k = 1; k < 16; k <<= 1)
        p += __shfl_xor_sync(0xffffffffu, p, k, 16);
    if (q == 0) S[r] = p;
}

// ---------------- layer-1 edge scatter (one warp per edge) ----------------
__global__ void edge_l1(const int* __restrict__ eu, const int* __restrict__ ei)
{
    int w = blockIdx.x * 8 + (threadIdx.x >> 5);
    if (w >= E_N) return;
    int lane = threadIdx.x & 31;
    int u = __ldg(eu + w);
    int i = __ldg(ei + w);
    int h = lane & 7;
    float x = g_work[SU1 + (size_t)u * 8 + h] + g_work[SI1 + (size_t)i * 8 + h];
    float lx = x >= 0.f ? x : 0.2f * x;
    float eh = expf(-lx);
    int c = lane & 15;
    float ehc = __shfl_sync(0xffffffffu, eh, c >> 1);
    if (lane < 16) {
        float4 v = ((const float4*)(g_work + IH1))[(size_t)i * 16 + c];
        red4(g_acc + AGGI1 + ((size_t)u * 16 + c) * 4,
             ehc * v.x, ehc * v.y, ehc * v.z, ehc * v.w);
        if (lane < 8) atomicAdd(g_acc + RS1 + (size_t)u * 8 + lane, eh);
    } else {
        float4 v = ((const float4*)(g_work + UH1))[(size_t)u * 16 + c];
        red4(g_acc + AGGU1 + ((size_t)i * 16 + c) * 4,
             ehc * v.x, ehc * v.y, ehc * v.z, ehc * v.w);
        if (lane < 24) atomicAdd(g_acc + CS1 + (size_t)i * 8 + (lane & 7), eh);
    }
}

// ---------------- layer-2 edge scatter ----------------
__global__ void edge_l2(const int* __restrict__ eu, const int* __restrict__ ei)
{
    int w = blockIdx.x * 8 + (threadIdx.x >> 5);
    if (w >= E_N) return;
    int lane = threadIdx.x & 31;
    int u = __ldg(eu + w);
    int i = __ldg(ei + w);
    float x = g_work[SU2 + u] + g_work[SI2 + i];
    float lx = x >= 0.f ? x : 0.2f * x;
    float eh = expf(-lx);
    int c = lane & 15;
    if (lane < 16) {
        float4 v = ((const float4*)(g_work + IH2))[(size_t)i * 16 + c];
        red4(g_acc + AGGI2 + ((size_t)u * 16 + c) * 4,
             eh * v.x, eh * v.y, eh * v.z, eh * v.w);
        if (lane == 0) atomicAdd(g_acc + RS2 + u, eh);
    } else {
        float4 v = ((const float4*)(g_work + UH2))[(size_t)u * 16 + c];
        red4(g_acc + AGGU2 + ((size_t)i * 16 + c) * 4,
             eh * v.x, eh * v.y, eh * v.z, eh * v.w);
        if (lane == 16) atomicAdd(g_acc + CS2 + i, eh);
    }
}

// ---------------- layer-1 epilogue: normalize + elu -> next-layer features --
__global__ void epilogue1(const float* __restrict__ X, const float* __restrict__ AGG,
                          const float* __restrict__ SUM, float* __restrict__ OUT, int n4)
{
    int idx = blockIdx.x * blockDim.x + threadIdx.x;
    if (idx >= n4) return;
    int r = idx >> 4, c4 = idx & 15, h = c4 >> 1;
    float s = SUM[(size_t)r * 8 + h];
    float inv = 1.f / ((s == 0.f) ? 1.f : s);
    float4 xv = ((const float4*)X)[idx];
    float4 av = ((const float4*)AGG)[idx];
    float4 o;
    o.x = elu1(xv.x + av.x * inv);
    o.y = elu1(xv.y + av.y * inv);
    o.z = elu1(xv.z + av.z * inv);
    o.w = elu1(xv.w + av.w * inv);
    ((float4*)OUT)[idx] = o;
}

// ---------------- final: gather rows, elu, dot ----------------
__global__ void final_k(const int* __restrict__ uIdx, const int* __restrict__ iIdx,
                        float* __restrict__ out)
{
    int b = blockIdx.x * 8 + (threadIdx.x >> 5);
    if (b >= B_N) return;
    int lane = threadIdx.x & 31;
    int u = uIdx[b], i = iIdx[b];
    float rs = g_acc[RS2 + u];
    float rinv = 1.f / ((rs == 0.f) ? 1.f : rs);
    float cs = g_acc[CS2 + i];
    float cinv = 1.f / ((cs == 0.f) ? 1.f : cs);
    float acc = 0.f;
#pragma unroll
    for (int t = 0; t < 2; t++) {
        int k = lane + t * 32;
        float uv = g_work[UH2 + (size_t)u * 64 + k] + g_acc[AGGI2 + (size_t)u * 64 + k] * rinv;
        uv = elu1(uv);
        float iv = g_work[IH2 + (size_t)i * 64 + k] + g_acc[AGGU2 + (size_t)i * 64 + k] * cinv;
        iv = elu1(iv);
        acc += uv * iv;
    }
#pragma unroll
    for (int k = 16; k >= 1; k >>= 1)
        acc += __shfl_xor_sync(0xffffffffu, acc, k);
    if (lane == 0) out[b] = acc;
}

// ---------------- launch ----------------
extern "C" void kernel_launch(void* const* d_in, const int* in_sizes, int n_in,
                              void* d_out, int out_size)
{
    const int*   userIdx = (const int*)d_in[0];
    const int*   itemIdx = (const int*)d_in[1];
    const int*   edge_u  = (const int*)d_in[2];
    const int*   edge_i  = (const int*)d_in[3];
    const float* uEmbd   = (const float*)d_in[4];
    const float* iEmbd   = (const float*)d_in[5];
    const float* Wu_h    = (const float*)d_in[6];
    const float* Wi_h    = (const float*)d_in[7];
    const float* a_h     = (const float*)d_in[8];
    const float* Wu_out  = (const float*)d_in[9];
    const float* Wi_out  = (const float*)d_in[10];
    const float* a_out   = (const float*)d_in[11];
    float* out = (float*)d_out;

    void *wp = nullptr, *ap = nullptr;
    cudaGetSymbolAddress(&wp, g_work);
    cudaGetSymbolAddress(&ap, g_acc);
    float* W = (float*)wp;

    cudaMemsetAsync(ap, 0, sizeof(float) * ACC_FLOATS, 0);

    // layer 1 transforms + per-head scores
    gemm_l1<<<U_N / 16, 256>>>(uEmbd, Wu_h, a_h, 0, W + UH1, W + SU1);
    gemm_l1<<<I_N / 16, 256>>>(iEmbd, Wi_h, a_h, 8, W + IH1, W + SI1);

    // layer 1 edge aggregation
    edge_l1<<<(E_N + 7) / 8, 256>>>(edge_u, edge_i);

    // layer 1 epilogue -> hu / hi
    epilogue1<<<(U_N * 16 + 255) / 256, 256>>>(W + UH1, (float*)ap + AGGI1,
                                               (float*)ap + RS1, W + HUo, U_N * 16);
    epilogue1<<<(I_N * 16 + 255) / 256, 256>>>(W + IH1, (float*)ap + AGGU1,
                                               (float*)ap + CS1, W + HIo, I_N * 16);

    // layer 2 transforms + scalar scores
    gemm_l2<<<U_N / 16, 256>>>(W + HUo, Wu_out, a_out, 0,  W + UH2, W + SU2);
    gemm_l2<<<I_N / 16, 256>>>(W + HIo, Wi_out, a_out, 64, W + IH2, W + SI2);

    // layer 2 edge aggregation
    edge_l2<<<(E_N + 7) / 8, 256>>>(edge_u, edge_i);

    // final gather + elu + dot
    final_k<<<(B_N + 7) / 8, 256>>>(userIdx, itemIdx, out);
}

// round 4
// speedup vs baseline: 1.2395x; 1.2395x over previous
#include <cuda_runtime.h>
#include <cstddef>

#define U_N 50000
#define I_N 100000
#define E_N 1600000
#define B_N 16384
#define RSTRIDE 72   // 64 features + 8 score slots = 288B = 9 sectors

// ---------------- float scratch (never needs zeroing) ----------------
constexpr size_t UH1 = 0;                                  // U*72
constexpr size_t IH1 = UH1 + (size_t)U_N * RSTRIDE;        // I*72
constexpr size_t HUo = IH1 + (size_t)I_N * RSTRIDE;        // U*72
constexpr size_t HIo = HUo + (size_t)U_N * RSTRIDE;        // I*72
constexpr size_t UH2 = HIo + (size_t)I_N * RSTRIDE;        // U*72
constexpr size_t IH2 = UH2 + (size_t)U_N * RSTRIDE;        // I*72
constexpr size_t UF_ = IH2 + (size_t)I_N * RSTRIDE;        // U*64 final user feats
constexpr size_t IF_ = UF_ + (size_t)U_N * 64;             // I*64 final item feats
constexpr size_t WORK_FLOATS = IF_ + (size_t)I_N * 64;     // 42,000,000 floats

// ---------------- int scratch (CSR) ----------------
constexpr size_t CNT_U = 0;            // 50000   } zeroed together (150000 ints)
constexpr size_t CNT_I = 50000;        // 100000  }
constexpr size_t OFF_U = 150016;       // 50001
constexpr size_t OFF_I = 200064;       // 100001
constexpr size_t CUR_U = 300160;       // 50000
constexpr size_t CUR_I = 350208;       // 100000
constexpr size_t LST_U = 450304;       // E
constexpr size_t LST_I = 2050304;      // E
constexpr size_t IDX_INTS = 3650304;

__device__ __align__(16) float g_work[WORK_FLOATS];
__device__ __align__(16) int   g_idx[IDX_INTS];

__device__ __forceinline__ float elu1(float x) {
    return x > 0.f ? x : expm1f(x);
}

// ---------------- CSR build ----------------
__global__ void hist_k(const int* __restrict__ eu, const int* __restrict__ ei)
{
    int e = blockIdx.x * 256 + threadIdx.x;
    if (e >= E_N) return;
    atomicAdd(&g_idx[CNT_U + eu[e]], 1);
    atomicAdd(&g_idx[CNT_I + ei[e]], 1);
}

// single-block exclusive scan: off[i] = prefix, off[n] = total, cur[i] = off[i]
__global__ void scan_k(const int* __restrict__ cnt, int* __restrict__ off,
                       int* __restrict__ cur, int n)
{
    __shared__ int wsum[32];
    __shared__ int s_carry;
    int tid = threadIdx.x;
    if (tid == 0) s_carry = 0;
    __syncthreads();
    for (int base = 0; base < n; base += 1024) {
        int i = base + tid;
        int v = (i < n) ? cnt[i] : 0;
        int x = v;
#pragma unroll
        for (int d = 1; d < 32; d <<= 1) {
            int t = __shfl_up_sync(0xffffffffu, x, d);
            if ((tid & 31) >= d) x += t;
        }
        if ((tid & 31) == 31) wsum[tid >> 5] = x;
        __syncthreads();
        if (tid < 32) {
            int w = wsum[tid];
#pragma unroll
            for (int d = 1; d < 32; d <<= 1) {
                int t = __shfl_up_sync(0xffffffffu, w, d);
                if (tid >= d) w += t;
            }
            wsum[tid] = w;
        }
        __syncthreads();
        int warp = tid >> 5;
        int excl = s_carry + (warp ? wsum[warp - 1] : 0) + x - v;
        if (i < n) { off[i] = excl; cur[i] = excl; }
        __syncthreads();
        if (tid == 0) s_carry += wsum[31];
        __syncthreads();
    }
    if (tid == 0) off[n] = s_carry;
}

__global__ void scat_k(const int* __restrict__ eu, const int* __restrict__ ei)
{
    int e = blockIdx.x * 256 + threadIdx.x;
    if (e >= E_N) return;
    int u = eu[e], i = ei[e];
    int pu = atomicAdd(&g_idx[CUR_U + u], 1);
    g_idx[LST_U + pu] = i;
    int pi = atomicAdd(&g_idx[CUR_I + i], 1);
    g_idx[LST_I + pi] = u;
}

// ---------------- layer-1 GEMM: [n,64] @ [8][64][8] + head scores ----------------
// Y row (stride 72): cols 0..63 = features, 64+h = score_h
__global__ void gemm_l1(const float* __restrict__ X,
                        const float* __restrict__ W,   // [8][64][8]
                        const float* __restrict__ a,   // [8][16]
                        int aoff,
                        float* __restrict__ Y)
{
    __shared__ float Ws[64 * 64];
    __shared__ float Es[16 * 64];
    int tid = threadIdx.x;
#pragma unroll
    for (int k = 0; k < 16; k++) {
        int idx = tid + k * 256;
        int d = idx >> 6, c = idx & 63;
        Ws[idx] = W[(c >> 3) * 512 + d * 8 + (c & 7)];
    }
    size_t r0 = (size_t)blockIdx.x * 16;
    {
        int tr = tid >> 4, q = tid & 15;
        ((float4*)Es)[tid] = *(const float4*)(X + (r0 + tr) * 64 + q * 4);
    }
    __syncthreads();

    int q = tid & 15;
    int tr = tid >> 4;
    float4 acc = make_float4(0.f, 0.f, 0.f, 0.f);
    const float4* Ws4 = (const float4*)Ws;
#pragma unroll
    for (int d = 0; d < 64; d++) {
        float e = Es[tr * 64 + d];
        float4 w = Ws4[d * 16 + q];
        acc.x += e * w.x; acc.y += e * w.y; acc.z += e * w.z; acc.w += e * w.w;
    }
    size_t r = r0 + tr;
    float* Yrow = Y + r * RSTRIDE;
    ((float4*)Yrow)[q] = acc;
    int h = q >> 1;
    const float* ap = a + h * 16 + aoff + (q & 1) * 4;
    float p = acc.x * ap[0] + acc.y * ap[1] + acc.z * ap[2] + acc.w * ap[3];
    p += __shfl_xor_sync(0xffffffffu, p, 1);
    if ((q & 1) == 0) Yrow[64 + h] = p;
}

// ---------------- layer-2 GEMM: [n,64]@[64,64] + scalar score ----------------
__global__ void gemm_l2(const float* __restrict__ X,   // stride 72
                        const float* __restrict__ W,   // [64][64]
                        const float* __restrict__ a,   // [128]
                        int aoff,
                        float* __restrict__ Y)
{
    __shared__ float Ws[64 * 64];
    __shared__ float Es[16 * 64];
    int tid = threadIdx.x;
#pragma unroll
    for (int k = 0; k < 4; k++)
        ((float4*)Ws)[tid + k * 256] = ((const float4*)W)[tid + k * 256];
    size_t r0 = (size_t)blockIdx.x * 16;
    {
        int tr = tid >> 4, q = tid & 15;
        ((float4*)Es)[tid] = *(const float4*)(X + (r0 + tr) * RSTRIDE + q * 4);
    }
    __syncthreads();

    int q = tid & 15;
    int tr = tid >> 4;
    float4 acc = make_float4(0.f, 0.f, 0.f, 0.f);
    const float4* Ws4 = (const float4*)Ws;
#pragma unroll
    for (int k = 0; k < 64; k++) {
        float e = Es[tr * 64 + k];
        float4 w = Ws4[k * 16 + q];
        acc.x += e * w.x; acc.y += e * w.y; acc.z += e * w.z; acc.w += e * w.w;
    }
    size_t r = r0 + tr;
    float* Yrow = Y + r * RSTRIDE;
    ((float4*)Yrow)[q] = acc;
    const float* ap = a + aoff + q * 4;
    float p = acc.x * ap[0] + acc.y * ap[1] + acc.z * ap[2] + acc.w * ap[3];
#pragma unroll
    for (int k = 1; k < 16; k <<= 1)
        p += __shfl_xor_sync(0xffffffffu, p, k, 16);
    if (q == 0) Yrow[64] = p;
}

// ---------------- CSR aggregation + normalize + elu (fused epilogue) ----------
// L=1: 8 heads (score slot 64+h, h=lane>>2); L=2: scalar score (slot 64)
// OUT row stride = ostride; writes elu(self + agg/rowsum)
template<int L>
__global__ void agg_k(const float* __restrict__ SELF, const float* __restrict__ PEER,
                      const int* __restrict__ off, const int* __restrict__ lst,
                      float* __restrict__ OUT, int ostride, int n)
{
    int node = blockIdx.x * 8 + (threadIdx.x >> 5);
    if (node >= n) return;
    int lane = threadIdx.x & 31;
    const float* self = SELF + (size_t)node * RSTRIDE;
    float s_own = (L == 1) ? self[64 + (lane >> 2)] : self[64];
    int o0 = off[node], o1 = off[node + 1];
    float2 acc = make_float2(0.f, 0.f);
    float rsum = 0.f;
    for (int base = o0; base < o1; base += 32) {
        int idx = (base + lane < o1) ? lst[base + lane] : 0;
        int m = min(32, o1 - base);
#pragma unroll 4
        for (int j = 0; j < m; j++) {
            int p = __shfl_sync(0xffffffffu, idx, j);
            const float* peer = PEER + (size_t)p * RSTRIDE;
            float sp = (L == 1) ? __ldg(peer + 64 + (lane >> 2)) : __ldg(peer + 64);
            float x = s_own + sp;
            float lx = x >= 0.f ? x : 0.2f * x;
            float e = __expf(-lx);
            float2 f = *(const float2*)(peer + 2 * lane);
            acc.x += e * f.x;
            acc.y += e * f.y;
            rsum += e;
        }
    }
    // lane's rsum == rowsum for its head (L=1) / the rowsum (L=2)
    float inv = (rsum > 0.f) ? 1.f / rsum : 0.f;
    float2 sf = *(const float2*)(self + 2 * lane);
    float2 o;
    o.x = elu1(sf.x + acc.x * inv);
    o.y = elu1(sf.y + acc.y * inv);
    *(float2*)(OUT + (size_t)node * ostride + 2 * lane) = o;
}

// ---------------- final: gather rows, dot ----------------
__global__ void final_k(const int* __restrict__ uIdx, const int* __restrict__ iIdx,
                        float* __restrict__ out)
{
    int b = blockIdx.x * 8 + (threadIdx.x >> 5);
    if (b >= B_N) return;
    int lane = threadIdx.x & 31;
    int u = uIdx[b], i = iIdx[b];
    const float* uf = g_work + UF_ + (size_t)u * 64;
    const float* if_ = g_work + IF_ + (size_t)i * 64;
    float acc = uf[lane] * if_[lane] + uf[lane + 32] * if_[lane + 32];
#pragma unroll
    for (int k = 16; k >= 1; k >>= 1)
        acc += __shfl_xor_sync(0xffffffffu, acc, k);
    if (lane == 0) out[b] = acc;
}

// ---------------- launch ----------------
extern "C" void kernel_launch(void* const* d_in, const int* in_sizes, int n_in,
                              void* d_out, int out_size)
{
    const int*   userIdx = (const int*)d_in[0];
    const int*   itemIdx = (const int*)d_in[1];
    const int*   edge_u  = (const int*)d_in[2];
    const int*   edge_i  = (const int*)d_in[3];
    const float* uEmbd   = (const float*)d_in[4];
    const float* iEmbd   = (const float*)d_in[5];
    const float* Wu_h    = (const float*)d_in[6];
    const float* Wi_h    = (const float*)d_in[7];
    const float* a_h     = (const float*)d_in[8];
    const float* Wu_out  = (const float*)d_in[9];
    const float* Wi_out  = (const float*)d_in[10];
    const float* a_out   = (const float*)d_in[11];
    float* out = (float*)d_out;

    void *wp = nullptr, *ip = nullptr;
    cudaGetSymbolAddress(&wp, g_work);
    cudaGetSymbolAddress(&ip, g_idx);
    float* W = (float*)wp;
    int*   X = (int*)ip;

    // --- CSR build (shared by both layers) ---
    cudaMemsetAsync(X + CNT_U, 0, 150000 * sizeof(int), 0);
    hist_k<<<(E_N + 255) / 256, 256>>>(edge_u, edge_i);
    scan_k<<<1, 1024>>>(X + CNT_U, X + OFF_U, X + CUR_U, U_N);
    scan_k<<<1, 1024>>>(X + CNT_I, X + OFF_I, X + CUR_I, I_N);
    scat_k<<<(E_N + 255) / 256, 256>>>(edge_u, edge_i);

    // --- layer 1 transforms (features + head scores in one row) ---
    gemm_l1<<<U_N / 16, 256>>>(uEmbd, Wu_h, a_h, 0, W + UH1);
    gemm_l1<<<I_N / 16, 256>>>(iEmbd, Wi_h, a_h, 8, W + IH1);

    // --- layer 1 aggregation (fused normalize + elu) ---
    agg_k<1><<<(U_N + 7) / 8, 256>>>(W + UH1, W + IH1, X + OFF_U, X + LST_U,
                                     W + HUo, RSTRIDE, U_N);
    agg_k<1><<<(I_N + 7) / 8, 256>>>(W + IH1, W + UH1, X + OFF_I, X + LST_I,
                                     W + HIo, RSTRIDE, I_N);

    // --- layer 2 transforms ---
    gemm_l2<<<U_N / 16, 256>>>(W + HUo, Wu_out, a_out, 0,  W + UH2);
    gemm_l2<<<I_N / 16, 256>>>(W + HIo, Wi_out, a_out, 64, W + IH2);

    // --- layer 2 aggregation (fused final elu) ---
    agg_k<2><<<(U_N + 7) / 8, 256>>>(W + UH2, W + IH2, X + OFF_U, X + LST_U,
                                     W + UF_, 64, U_N);
    agg_k<2><<<(I_N + 7) / 8, 256>>>(W + IH2, W + UH2, X + OFF_I, X + LST_I,
                                     W + IF_, 64, I_N);

    // --- final gather + dot ---
    final_k<<<(B_N + 7) / 8, 256>>>(userIdx, itemIdx, out);
}

// round 6
// speedup vs baseline: 1.2827x; 1.0348x over previous
#include <cuda_runtime.h>
#include <cstddef>

#define U_N 50000
#define I_N 100000
#define E_N 1600000
#define B_N 16384
#define RSTRIDE 72   // 64 features + 8 score slots = 288B = 9 sectors

// ---------------- float scratch (never needs zeroing) ----------------
constexpr size_t UH1 = 0;                                  // U*72
constexpr size_t IH1 = UH1 + (size_t)U_N * RSTRIDE;        // I*72
constexpr size_t HUo = IH1 + (size_t)I_N * RSTRIDE;        // U*72
constexpr size_t HIo = HUo + (size_t)U_N * RSTRIDE;        // I*72
constexpr size_t UH2 = HIo + (size_t)I_N * RSTRIDE;        // U*72
constexpr size_t IH2 = UH2 + (size_t)U_N * RSTRIDE;        // I*72
constexpr size_t UF_ = IH2 + (size_t)I_N * RSTRIDE;        // U*64 final user feats
constexpr size_t IF_ = UF_ + (size_t)U_N * 64;             // I*64 final item feats
constexpr size_t WORK_FLOATS = IF_ + (size_t)I_N * 64;

// ---------------- int scratch ----------------
// zeroed region (one memset): counts + needed-node flags
constexpr size_t CNT_U = 0;            // 50000
constexpr size_t CNT_I = 50000;        // 100000
constexpr size_t FLG_U = 150000;       // 50000
constexpr size_t FLG_I = 200000;       // 100000
constexpr size_t ZERO_INTS = 300000;
constexpr size_t OFF_U = 300000;       // 50001
constexpr size_t OFF_I = 350016;       // 100001
constexpr size_t CUR_U = 450112;       // 50000
constexpr size_t CUR_I = 500112;       // 100000
constexpr size_t LST_U = 600112;       // E
constexpr size_t LST_I = 2200112;      // E
constexpr size_t IDX_INTS = 3800112;

__device__ __align__(16) float g_work[WORK_FLOATS];
__device__ __align__(16) int   g_idx[IDX_INTS];

__device__ __forceinline__ float elu1(float x) {
    return x > 0.f ? x : expm1f(x);
}

// ---------------- CSR build ----------------
// 4 edges per thread -> 8 independent atomic chains (latency hiding)
__global__ void hist_k(const int* __restrict__ eu, const int* __restrict__ ei)
{
    int t = blockIdx.x * 256 + threadIdx.x;
    if (t >= E_N / 4) return;
#pragma unroll
    for (int k = 0; k < 4; k++) {
        int e = t + k * (E_N / 4);
        atomicAdd(&g_idx[CNT_U + __ldg(eu + e)], 1);
        atomicAdd(&g_idx[CNT_I + __ldg(ei + e)], 1);
    }
}

// single-block exclusive scan: off[i] = prefix, off[n] = total, cur[i] = off[i]
__global__ void scan_k(const int* __restrict__ cnt, int* __restrict__ off,
                       int* __restrict__ cur, int n)
{
    __shared__ int wsum[32];
    __shared__ int s_carry;
    int tid = threadIdx.x;
    if (tid == 0) s_carry = 0;
    __syncthreads();
    for (int base = 0; base < n; base += 1024) {
        int i = base + tid;
        int v = (i < n) ? cnt[i] : 0;
        int x = v;
#pragma unroll
        for (int d = 1; d < 32; d <<= 1) {
            int t = __shfl_up_sync(0xffffffffu, x, d);
            if ((tid & 31) >= d) x += t;
        }
        if ((tid & 31) == 31) wsum[tid >> 5] = x;
        __syncthreads();
        if (tid < 32) {
            int w = wsum[tid];
#pragma unroll
            for (int d = 1; d < 32; d <<= 1) {
                int t = __shfl_up_sync(0xffffffffu, w, d);
                if (tid >= d) w += t;
            }
            wsum[tid] = w;
        }
        __syncthreads();
        int warp = tid >> 5;
        int excl = s_carry + (warp ? wsum[warp - 1] : 0) + x - v;
        if (i < n) { off[i] = excl; cur[i] = excl; }
        __syncthreads();
        if (tid == 0) s_carry += wsum[31];
        __syncthreads();
    }
    if (tid == 0) off[n] = s_carry;
}

__global__ void scat_k(const int* __restrict__ eu, const int* __restrict__ ei)
{
    int t = blockIdx.x * 256 + threadIdx.x;
    if (t >= E_N / 4) return;
#pragma unroll
    for (int k = 0; k < 4; k++) {
        int e = t + k * (E_N / 4);
        int u = __ldg(eu + e), i = __ldg(ei + e);
        int pu = atomicAdd(&g_idx[CUR_U + u], 1);
        g_idx[LST_U + pu] = i;
        int pi = atomicAdd(&g_idx[CUR_I + i], 1);
        g_idx[LST_I + pi] = u;
    }
}

// mark nodes actually consumed by the final dot
__global__ void mark_k(const int* __restrict__ uIdx, const int* __restrict__ iIdx)
{
    int t = blockIdx.x * 256 + threadIdx.x;
    if (t >= B_N) return;
    g_idx[FLG_U + uIdx[t]] = 1;
    g_idx[FLG_I + iIdx[t]] = 1;
}

// ---------------- layer-1 GEMM: [n,64] @ [8][64][8] + head scores ----------------
// 64 rows per block (weight tile loaded once, reused 4x)
__global__ void gemm_l1(const float* __restrict__ X,
                        const float* __restrict__ W,   // [8][64][8]
                        const float* __restrict__ a,   // [8][16]
                        int aoff,
                        float* __restrict__ Y, int n)
{
    __shared__ float Ws[64 * 64];
    __shared__ float Es[16 * 64];
    int tid = threadIdx.x;
#pragma unroll
    for (int k = 0; k < 16; k++) {
        int idx = tid + k * 256;
        int d = idx >> 6, c = idx & 63;
        Ws[idx] = W[(c >> 3) * 512 + d * 8 + (c & 7)];
    }
    int q = tid & 15;
    int tr = tid >> 4;
    const float4* Ws4 = (const float4*)Ws;
#pragma unroll
    for (int it = 0; it < 4; it++) {
        size_t r0 = ((size_t)blockIdx.x * 4 + it) * 16;
        if (r0 >= (size_t)n) return;
        __syncthreads();
        ((float4*)Es)[tid] = *(const float4*)(X + (r0 + tr) * 64 + q * 4);
        __syncthreads();
        float4 acc = make_float4(0.f, 0.f, 0.f, 0.f);
#pragma unroll
        for (int d = 0; d < 64; d++) {
            float e = Es[tr * 64 + d];
            float4 w = Ws4[d * 16 + q];
            acc.x += e * w.x; acc.y += e * w.y; acc.z += e * w.z; acc.w += e * w.w;
        }
        float* Yrow = Y + (r0 + tr) * RSTRIDE;
        ((float4*)Yrow)[q] = acc;
        int h = q >> 1;
        const float* ap = a + h * 16 + aoff + (q & 1) * 4;
        float p = acc.x * ap[0] + acc.y * ap[1] + acc.z * ap[2] + acc.w * ap[3];
        p += __shfl_xor_sync(0xffffffffu, p, 1);
        if ((q & 1) == 0) Yrow[64 + h] = p;
    }
}

// ---------------- layer-2 GEMM: [n,64]@[64,64] + scalar score ----------------
__global__ void gemm_l2(const float* __restrict__ X,   // stride 72
                        const float* __restrict__ W,   // [64][64]
                        const float* __restrict__ a,   // [128]
                        int aoff,
                        float* __restrict__ Y, int n)
{
    __shared__ float Ws[64 * 64];
    __shared__ float Es[16 * 64];
    int tid = threadIdx.x;
#pragma unroll
    for (int k = 0; k < 4; k++)
        ((float4*)Ws)[tid + k * 256] = ((const float4*)W)[tid + k * 256];
    int q = tid & 15;
    int tr = tid >> 4;
    const float4* Ws4 = (const float4*)Ws;
#pragma unroll
    for (int it = 0; it < 4; it++) {
        size_t r0 = ((size_t)blockIdx.x * 4 + it) * 16;
        if (r0 >= (size_t)n) return;
        __syncthreads();
        ((float4*)Es)[tid] = *(const float4*)(X + (r0 + tr) * RSTRIDE + q * 4);
        __syncthreads();
        float4 acc = make_float4(0.f, 0.f, 0.f, 0.f);
#pragma unroll
        for (int k = 0; k < 64; k++) {
            float e = Es[tr * 64 + k];
            float4 w = Ws4[k * 16 + q];
            acc.x += e * w.x; acc.y += e * w.y; acc.z += e * w.z; acc.w += e * w.w;
        }
        float* Yrow = Y + (r0 + tr) * RSTRIDE;
        ((float4*)Yrow)[q] = acc;
        const float* ap = a + aoff + q * 4;
        float p = acc.x * ap[0] + acc.y * ap[1] + acc.z * ap[2] + acc.w * ap[3];
#pragma unroll
        for (int k = 1; k < 16; k <<= 1)
            p += __shfl_xor_sync(0xffffffffu, p, k, 16);
        if (q == 0) Yrow[64] = p;
    }
}

// ---------------- CSR aggregation + normalize + elu (fused epilogue) ----------
// Two-phase: A) every lane loads one score & computes e (high MLP);
//            B) unrolled accumulation, e via shfl (no dependent score load).
// L=1: 8 heads (lane accumulates cols 2l,2l+1; head = lane>>2)
// L=2: scalar score; FLAG filters nodes not consumed downstream.
template<int L, bool FILTER>
__global__ void agg_k(const float* __restrict__ SELF, const float* __restrict__ PEER,
                      const int* __restrict__ off, const int* __restrict__ lst,
                      const int* __restrict__ flag,
                      float* __restrict__ OUT, int ostride, int n)
{
    int node = blockIdx.x * 8 + (threadIdx.x >> 5);
    if (node >= n) return;
    if (FILTER && !__ldg(flag + node)) return;
    int lane = threadIdx.x & 31;
    const float* self = SELF + (size_t)node * RSTRIDE;
    // phase-A score role: L1 -> head (lane&7); L2 -> scalar
    float sA = (L == 1) ? self[64 + (lane & 7)] : self[64];
    int o0 = __ldg(off + node), o1 = __ldg(off + node + 1);
    float2 acc = make_float2(0.f, 0.f);
    float rsum = 0.f;

    for (int base = o0; base < o1; base += 32) {
        int rem = o1 - base;                       // >0
        int idx = (lane < rem) ? __ldg(lst + base + lane) : 0;

        float epack[L == 1 ? 8 : 1];
        if (L == 1) {
            // subchunk s covers edges s*4..s*4+3; lane handles edge s*4+(lane>>3), head lane&7
#pragma unroll
            for (int s = 0; s < 8; s++) {
                int j = s * 4 + (lane >> 3);
                int p = __shfl_sync(0xffffffffu, idx, j);
                float sp = (j < rem) ? __ldg(PEER + (size_t)p * RSTRIDE + 64 + (lane & 7)) : 0.f;
                float x = sA + sp;
                float lx = x >= 0.f ? x : 0.2f * x;
                epack[s] = (j < rem) ? __expf(-lx) : 0.f;
            }
        } else {
            // lane computes e for edge base+lane
            float sp = (lane < rem) ? __ldg(PEER + (size_t)idx * RSTRIDE + 64) : 0.f;
            float x = sA + sp;
            float lx = x >= 0.f ? x : 0.2f * x;
            epack[0] = (lane < rem) ? __expf(-lx) : 0.f;
        }

#pragma unroll
        for (int j = 0; j < 32; j++) {
            int p = __shfl_sync(0xffffffffu, idx, j);
            float eh = (L == 1)
                ? __shfl_sync(0xffffffffu, epack[j >> 2], (j & 3) * 8 + (lane >> 2))
                : __shfl_sync(0xffffffffu, epack[0], j);
            if (j < rem) {
                float2 f = *(const float2*)(PEER + (size_t)p * RSTRIDE + 2 * lane);
                acc.x += eh * f.x;
                acc.y += eh * f.y;
                rsum += eh;
            }
        }
    }
    // lane's rsum == rowsum for its head (L=1) / the rowsum (L=2)
    float inv = (rsum > 0.f) ? 1.f / rsum : 0.f;
    float2 sf = *(const float2*)(self + 2 * lane);
    float2 o;
    o.x = elu1(sf.x + acc.x * inv);
    o.y = elu1(sf.y + acc.y * inv);
    *(float2*)(OUT + (size_t)node * ostride + 2 * lane) = o;
}

// ---------------- final: gather rows, dot ----------------
__global__ void final_k(const int* __restrict__ uIdx, const int* __restrict__ iIdx,
                        float* __restrict__ out)
{
    int b = blockIdx.x * 8 + (threadIdx.x >> 5);
    if (b >= B_N) return;
    int lane = threadIdx.x & 31;
    int u = uIdx[b], i = iIdx[b];
    const float* uf = g_work + UF_ + (size_t)u * 64;
    const float* if_ = g_work + IF_ + (size_t)i * 64;
    float acc = uf[lane] * if_[lane] + uf[lane + 32] * if_[lane + 32];
#pragma unroll
    for (int k = 16; k >= 1; k >>= 1)
        acc += __shfl_xor_sync(0xffffffffu, acc, k);
    if (lane == 0) out[b] = acc;
}

// ---------------- launch ----------------
extern "C" void kernel_launch(void* const* d_in, const int* in_sizes, int n_in,
                              void* d_out, int out_size)
{
    const int*   userIdx = (const int*)d_in[0];
    const int*   itemIdx = (const int*)d_in[1];
    const int*   edge_u  = (const int*)d_in[2];
    const int*   edge_i  = (const int*)d_in[3];
    const float* uEmbd   = (const float*)d_in[4];
    const float* iEmbd   = (const float*)d_in[5];
    const float* Wu_h    = (const float*)d_in[6];
    const float* Wi_h    = (const float*)d_in[7];
    const float* a_h     = (const float*)d_in[8];
    const float* Wu_out  = (const float*)d_in[9];
    const float* Wi_out  = (const float*)d_in[10];
    const float* a_out   = (const float*)d_in[11];
    float* out = (float*)d_out;

    void *wp = nullptr, *ip = nullptr;
    cudaGetSymbolAddress(&wp, g_work);
    cudaGetSymbolAddress(&ip, g_idx);
    float* W = (float*)wp;
    int*   X = (int*)ip;

    // --- CSR build + needed-node flags ---
    cudaMemsetAsync(X + CNT_U, 0, ZERO_INTS * sizeof(int), 0);
    hist_k<<<(E_N / 4 + 255) / 256, 256>>>(edge_u, edge_i);
    mark_k<<<(B_N + 255) / 256, 256>>>(userIdx, itemIdx);
    scan_k<<<1, 1024>>>(X + CNT_U, X + OFF_U, X + CUR_U, U_N);
    scan_k<<<1, 1024>>>(X + CNT_I, X + OFF_I, X + CUR_I, I_N);
    scat_k<<<(E_N / 4 + 255) / 256, 256>>>(edge_u, edge_i);

    // --- layer 1 transforms (features + head scores in one row) ---
    gemm_l1<<<(U_N + 63) / 64, 256>>>(uEmbd, Wu_h, a_h, 0, W + UH1, U_N);
    gemm_l1<<<(I_N + 63) / 64, 256>>>(iEmbd, Wi_h, a_h, 8, W + IH1, I_N);

    // --- layer 1 aggregation (fused normalize + elu) ---
    agg_k<1, false><<<(U_N + 7) / 8, 256>>>(W + UH1, W + IH1, X + OFF_U, X + LST_U,
                                            nullptr, W + HUo, RSTRIDE, U_N);
    agg_k<1, false><<<(I_N + 7) / 8, 256>>>(W + IH1, W + UH1, X + OFF_I, X + LST_I,
                                            nullptr, W + HIo, RSTRIDE, I_N);

    // --- layer 2 transforms ---
    gemm_l2<<<(U_N + 63) / 64, 256>>>(W + HUo, Wu_out, a_out, 0,  W + UH2, U_N);
    gemm_l2<<<(I_N + 63) / 64, 256>>>(W + HIo, Wi_out, a_out, 64, W + IH2, I_N);

    // --- layer 2 aggregation (only nodes the final dot consumes) ---
    agg_k<2, true><<<(U_N + 7) / 8, 256>>>(W + UH2, W + IH2, X + OFF_U, X + LST_U,
                                           X + FLG_U, W + UF_, 64, U_N);
    agg_k<2, true><<<(I_N + 7) / 8, 256>>>(W + IH2, W + UH2, X + OFF_I, X + LST_I,
                                           X + FLG_I, W + IF_, 64, I_N);

    // --- final gather + dot ---
    final_k<<<(B_N + 7) / 8, 256>>>(userIdx, itemIdx, out);
}

// round 7
// speedup vs baseline: 1.6058x; 1.2519x over previous
#include <cuda_runtime.h>
#include <cstddef>

#define U_N 50000
#define I_N 100000
#define E_N 1600000
#define B_N 16384
#define RSTRIDE 72   // 64 features + 8 score slots = 288B = 9 sectors
#define N_ALL (U_N + I_N)          // 150000 combined nodes
#define SCAN_BLK 8192              // elems per scan block (1024 thr x 8)
#define SCAN_NB ((N_ALL + SCAN_BLK - 1) / SCAN_BLK)   // 19

// ---------------- float scratch (never needs zeroing) ----------------
constexpr size_t UH1 = 0;                                  // U*72
constexpr size_t IH1 = UH1 + (size_t)U_N * RSTRIDE;        // I*72
constexpr size_t HUo = IH1 + (size_t)I_N * RSTRIDE;        // U*72
constexpr size_t HIo = HUo + (size_t)U_N * RSTRIDE;        // I*72
constexpr size_t UH2 = HIo + (size_t)I_N * RSTRIDE;        // U*72
constexpr size_t IH2 = UH2 + (size_t)U_N * RSTRIDE;        // I*72
constexpr size_t UF_ = IH2 + (size_t)I_N * RSTRIDE;        // U*64 final user feats
constexpr size_t IF_ = UF_ + (size_t)U_N * 64;             // I*64 final item feats
constexpr size_t WORK_FLOATS = IF_ + (size_t)I_N * 64;

// ---------------- int scratch ----------------
// zeroed region (one memset): combined counts + needed-node flags
constexpr size_t CNT_A = 0;            // 150000 (users then items)
constexpr size_t FLG_U = 150000;       // 50000
constexpr size_t FLG_I = 200000;       // 100000
constexpr size_t ZERO_INTS = 300000;
constexpr size_t OFF_A = 300000;       // 150001 combined exclusive offsets
constexpr size_t CUR_A = 450112;       // 150000
constexpr size_t BSUM  = 600128;       // 32 block sums
constexpr size_t LST   = 600192;       // 2E combined edge lists
constexpr size_t IDX_INTS = LST + 2 * (size_t)E_N;

__device__ __align__(16) float g_work[WORK_FLOATS];
__device__ __align__(16) int   g_idx[IDX_INTS];

__device__ __forceinline__ float elu1(float x) {
    return x > 0.f ? x : expm1f(x);
}

// ---------------- CSR build ----------------
// 4 edges per thread -> 8 independent atomic chains (latency hiding)
__global__ void hist_k(const int* __restrict__ eu, const int* __restrict__ ei)
{
    int t = blockIdx.x * 256 + threadIdx.x;
    if (t >= E_N / 4) return;
#pragma unroll
    for (int k = 0; k < 4; k++) {
        int e = t + k * (E_N / 4);
        atomicAdd(&g_idx[CNT_A + __ldg(eu + e)], 1);
        atomicAdd(&g_idx[CNT_A + U_N + __ldg(ei + e)], 1);
    }
}

// ---- 3-phase multi-block exclusive scan over the combined counts ----
__global__ void scanA_k(const int* __restrict__ cnt, int* __restrict__ off,
                        int* __restrict__ bsum)
{
    __shared__ int wsum[32];
    int tid = threadIdx.x;
    int lane = tid & 31, warp = tid >> 5;
    int base = blockIdx.x * SCAN_BLK + tid * 8;
    int v[8];
    int s = 0;
#pragma unroll
    for (int k = 0; k < 8; k++) {
        v[k] = (base + k < N_ALL) ? cnt[base + k] : 0;
        s += v[k];
    }
    int x = s;
#pragma unroll
    for (int d = 1; d < 32; d <<= 1) {
        int t = __shfl_up_sync(0xffffffffu, x, d);
        if (lane >= d) x += t;
    }
    if (lane == 31) wsum[warp] = x;
    __syncthreads();
    if (tid < 32) {
        int w = wsum[tid];
#pragma unroll
        for (int d = 1; d < 32; d <<= 1) {
            int t = __shfl_up_sync(0xffffffffu, w, d);
            if (tid >= d) w += t;
        }
        wsum[tid] = w;
    }
    __syncthreads();
    int excl = (warp ? wsum[warp - 1] : 0) + x - s;   // exclusive prefix within block
#pragma unroll
    for (int k = 0; k < 8; k++) {
        if (base + k < N_ALL) off[base + k] = excl;
        excl += v[k];
    }
    if (tid == 0) bsum[blockIdx.x] = wsum[31];
}

__global__ void scanB_k(int* __restrict__ bsum)
{
    int tid = threadIdx.x;   // one warp
    int v = (tid < SCAN_NB) ? bsum[tid] : 0;
    int x = v;
#pragma unroll
    for (int d = 1; d < 32; d <<= 1) {
        int t = __shfl_up_sync(0xffffffffu, x, d);
        if (tid >= d) x += t;
    }
    if (tid < SCAN_NB) bsum[tid] = x - v;   // exclusive
}

__global__ void scanC_k(int* __restrict__ off, int* __restrict__ cur,
                        const int* __restrict__ bsum)
{
    int i = blockIdx.x * 1024 + threadIdx.x;
    if (i >= N_ALL) return;
    int o = off[i] + __ldg(bsum + (i / SCAN_BLK));
    off[i] = o;
    cur[i] = o;
    if (i == 0) off[N_ALL] = 2 * E_N;   // known total
}

__global__ void scat_k(const int* __restrict__ eu, const int* __restrict__ ei)
{
    int t = blockIdx.x * 256 + threadIdx.x;
    if (t >= E_N / 4) return;
#pragma unroll
    for (int k = 0; k < 4; k++) {
        int e = t + k * (E_N / 4);
        int u = __ldg(eu + e), i = __ldg(ei + e);
        int pu = atomicAdd(&g_idx[CUR_A + u], 1);
        g_idx[LST + pu] = i;
        int pi = atomicAdd(&g_idx[CUR_A + U_N + i], 1);
        g_idx[LST + pi] = u;
    }
}

// mark nodes actually consumed by the final dot
__global__ void mark_k(const int* __restrict__ uIdx, const int* __restrict__ iIdx)
{
    int t = blockIdx.x * 256 + threadIdx.x;
    if (t >= B_N) return;
    g_idx[FLG_U + uIdx[t]] = 1;
    g_idx[FLG_I + iIdx[t]] = 1;
}

// ---------------- layer-1 GEMM: [n,64] @ [8][64][8] + head scores ----------------
// 64 rows per block (weight tile loaded once, reused 4x)
__global__ void gemm_l1(const float* __restrict__ X,
                        const float* __restrict__ W,   // [8][64][8]
                        const float* __restrict__ a,   // [8][16]
                        int aoff,
                        float* __restrict__ Y, int n)
{
    __shared__ float Ws[64 * 64];
    __shared__ float Es[16 * 64];
    int tid = threadIdx.x;
#pragma unroll
    for (int k = 0; k < 16; k++) {
        int idx = tid + k * 256;
        int d = idx >> 6, c = idx & 63;
        Ws[idx] = W[(c >> 3) * 512 + d * 8 + (c & 7)];
    }
    int q = tid & 15;
    int tr = tid >> 4;
    const float4* Ws4 = (const float4*)Ws;
#pragma unroll
    for (int it = 0; it < 4; it++) {
        size_t r0 = ((size_t)blockIdx.x * 4 + it) * 16;
        if (r0 >= (size_t)n) return;
        __syncthreads();
        ((float4*)Es)[tid] = *(const float4*)(X + (r0 + tr) * 64 + q * 4);
        __syncthreads();
        float4 acc = make_float4(0.f, 0.f, 0.f, 0.f);
#pragma unroll
        for (int d = 0; d < 64; d++) {
            float e = Es[tr * 64 + d];
            float4 w = Ws4[d * 16 + q];
            acc.x += e * w.x; acc.y += e * w.y; acc.z += e * w.z; acc.w += e * w.w;
        }
        float* Yrow = Y + (r0 + tr) * RSTRIDE;
        ((float4*)Yrow)[q] = acc;
        int h = q >> 1;
        const float* ap = a + h * 16 + aoff + (q & 1) * 4;
        float p = acc.x * ap[0] + acc.y * ap[1] + acc.z * ap[2] + acc.w * ap[3];
        p += __shfl_xor_sync(0xffffffffu, p, 1);
        if ((q & 1) == 0) Yrow[64 + h] = p;
    }
}

// ---------------- layer-2 GEMM: [n,64]@[64,64] + scalar score ----------------
__global__ void gemm_l2(const float* __restrict__ X,   // stride 72
                        const float* __restrict__ W,   // [64][64]
                        const float* __restrict__ a,   // [128]
                        int aoff,
                        float* __restrict__ Y, int n)
{
    __shared__ float Ws[64 * 64];
    __shared__ float Es[16 * 64];
    int tid = threadIdx.x;
#pragma unroll
    for (int k = 0; k < 4; k++)
        ((float4*)Ws)[tid + k * 256] = ((const float4*)W)[tid + k * 256];
    int q = tid & 15;
    int tr = tid >> 4;
    const float4* Ws4 = (const float4*)Ws;
#pragma unroll
    for (int it = 0; it < 4; it++) {
        size_t r0 = ((size_t)blockIdx.x * 4 + it) * 16;
        if (r0 >= (size_t)n) return;
        __syncthreads();
        ((float4*)Es)[tid] = *(const float4*)(X + (r0 + tr) * RSTRIDE + q * 4);
        __syncthreads();
        float4 acc = make_float4(0.f, 0.f, 0.f, 0.f);
#pragma unroll
        for (int k = 0; k < 64; k++) {
            float e = Es[tr * 64 + k];
            float4 w = Ws4[k * 16 + q];
            acc.x += e * w.x; acc.y += e * w.y; acc.z += e * w.z; acc.w += e * w.w;
        }
        float* Yrow = Y + (r0 + tr) * RSTRIDE;
        ((float4*)Yrow)[q] = acc;
        const float* ap = a + aoff + q * 4;
        float p = acc.x * ap[0] + acc.y * ap[1] + acc.z * ap[2] + acc.w * ap[3];
#pragma unroll
        for (int k = 1; k < 16; k <<= 1)
            p += __shfl_xor_sync(0xffffffffu, p, k, 16);
        if (q == 0) Yrow[64] = p;
    }
}

// ---------------- CSR aggregation + normalize + elu (fused epilogue) ----------
// Two-phase: A) every lane loads one score & computes e (high MLP);
//            B) unrolled accumulation, e via shfl (no dependent score load).
// L=1: 8 heads (lane accumulates cols 2l,2l+1; head = lane>>2)
// L=2: scalar score; FLAG filters nodes not consumed downstream.
template<int L, bool FILTER>
__global__ void agg_k(const float* __restrict__ SELF, const float* __restrict__ PEER,
                      const int* __restrict__ off, const int* __restrict__ lst,
                      const int* __restrict__ flag,
                      float* __restrict__ OUT, int ostride, int n)
{
    int node = blockIdx.x * 8 + (threadIdx.x >> 5);
    if (node >= n) return;
    if (FILTER && !__ldg(flag + node)) return;
    int lane = threadIdx.x & 31;
    const float* self = SELF + (size_t)node * RSTRIDE;
    // phase-A score role: L1 -> head (lane&7); L2 -> scalar
    float sA = (L == 1) ? self[64 + (lane & 7)] : self[64];
    int o0 = __ldg(off + node), o1 = __ldg(off + node + 1);
    float2 acc = make_float2(0.f, 0.f);
    float rsum = 0.f;

    for (int base = o0; base < o1; base += 32) {
        int rem = o1 - base;                       // >0
        int idx = (lane < rem) ? __ldg(lst + base + lane) : 0;

        float epack[L == 1 ? 8 : 1];
        if (L == 1) {
            // subchunk s covers edges s*4..s*4+3; lane handles edge s*4+(lane>>3), head lane&7
#pragma unroll
            for (int s = 0; s < 8; s++) {
                int j = s * 4 + (lane >> 3);
                int p = __shfl_sync(0xffffffffu, idx, j);
                float sp = (j < rem) ? __ldg(PEER + (size_t)p * RSTRIDE + 64 + (lane & 7)) : 0.f;
                float x = sA + sp;
                float lx = x >= 0.f ? x : 0.2f * x;
                epack[s] = (j < rem) ? __expf(-lx) : 0.f;
            }
        } else {
            // lane computes e for edge base+lane
            float sp = (lane < rem) ? __ldg(PEER + (size_t)idx * RSTRIDE + 64) : 0.f;
            float x = sA + sp;
            float lx = x >= 0.f ? x : 0.2f * x;
            epack[0] = (lane < rem) ? __expf(-lx) : 0.f;
        }

#pragma unroll
        for (int j = 0; j < 32; j++) {
            int p = __shfl_sync(0xffffffffu, idx, j);
            float eh = (L == 1)
                ? __shfl_sync(0xffffffffu, epack[j >> 2], (j & 3) * 8 + (lane >> 2))
                : __shfl_sync(0xffffffffu, epack[0], j);
            if (j < rem) {
                float2 f = *(const float2*)(PEER + (size_t)p * RSTRIDE + 2 * lane);
                acc.x += eh * f.x;
                acc.y += eh * f.y;
                rsum += eh;
            }
        }
    }
    // lane's rsum == rowsum for its head (L=1) / the rowsum (L=2)
    float inv = (rsum > 0.f) ? 1.f / rsum : 0.f;
    float2 sf = *(const float2*)(self + 2 * lane);
    float2 o;
    o.x = elu1(sf.x + acc.x * inv);
    o.y = elu1(sf.y + acc.y * inv);
    *(float2*)(OUT + (size_t)node * ostride + 2 * lane) = o;
}

// ---------------- final: gather rows, dot ----------------
__global__ void final_k(const int* __restrict__ uIdx, const int* __restrict__ iIdx,
                        float* __restrict__ out)
{
    int b = blockIdx.x * 8 + (threadIdx.x >> 5);
    if (b >= B_N) return;
    int lane = threadIdx.x & 31;
    int u = uIdx[b], i = iIdx[b];
    const float* uf = g_work + UF_ + (size_t)u * 64;
    const float* if_ = g_work + IF_ + (size_t)i * 64;
    float acc = uf[lane] * if_[lane] + uf[lane + 32] * if_[lane + 32];
#pragma unroll
    for (int k = 16; k >= 1; k >>= 1)
        acc += __shfl_xor_sync(0xffffffffu, acc, k);
    if (lane == 0) out[b] = acc;
}

// ---------------- launch ----------------
extern "C" void kernel_launch(void* const* d_in, const int* in_sizes, int n_in,
                              void* d_out, int out_size)
{
    const int*   userIdx = (const int*)d_in[0];
    const int*   itemIdx = (const int*)d_in[1];
    const int*   edge_u  = (const int*)d_in[2];
    const int*   edge_i  = (const int*)d_in[3];
    const float* uEmbd   = (const float*)d_in[4];
    const float* iEmbd   = (const float*)d_in[5];
    const float* Wu_h    = (const float*)d_in[6];
    const float* Wi_h    = (const float*)d_in[7];
    const float* a_h     = (const float*)d_in[8];
    const float* Wu_out  = (const float*)d_in[9];
    const float* Wi_out  = (const float*)d_in[10];
    const float* a_out   = (const float*)d_in[11];
    float* out = (float*)d_out;

    void *wp = nullptr, *ip = nullptr;
    cudaGetSymbolAddress(&wp, g_work);
    cudaGetSymbolAddress(&ip, g_idx);
    float* W = (float*)wp;
    int*   X = (int*)ip;

    // --- CSR build (combined U+I scan, single contiguous edge list) ---
    cudaMemsetAsync(X + CNT_A, 0, ZERO_INTS * sizeof(int), 0);
    hist_k<<<(E_N / 4 + 255) / 256, 256>>>(edge_u, edge_i);
    mark_k<<<(B_N + 255) / 256, 256>>>(userIdx, itemIdx);
    scanA_k<<<SCAN_NB, 1024>>>(X + CNT_A, X + OFF_A, X + BSUM);
    scanB_k<<<1, 32>>>(X + BSUM);
    scanC_k<<<(N_ALL + 1023) / 1024, 1024>>>(X + OFF_A, X + CUR_A, X + BSUM);
    scat_k<<<(E_N / 4 + 255) / 256, 256>>>(edge_u, edge_i);

    // --- layer 1 transforms (features + head scores in one row) ---
    gemm_l1<<<(U_N + 63) / 64, 256>>>(uEmbd, Wu_h, a_h, 0, W + UH1, U_N);
    gemm_l1<<<(I_N + 63) / 64, 256>>>(iEmbd, Wi_h, a_h, 8, W + IH1, I_N);

    // --- layer 1 aggregation (fused normalize + elu) ---
    agg_k<1, false><<<(U_N + 7) / 8, 256>>>(W + UH1, W + IH1, X + OFF_A, X + LST,
                                            nullptr, W + HUo, RSTRIDE, U_N);
    agg_k<1, false><<<(I_N + 7) / 8, 256>>>(W + IH1, W + UH1, X + OFF_A + U_N, X + LST,
                                            nullptr, W + HIo, RSTRIDE, I_N);

    // --- layer 2 transforms ---
    gemm_l2<<<(U_N + 63) / 64, 256>>>(W + HUo, Wu_out, a_out, 0,  W + UH2, U_N);
    gemm_l2<<<(I_N + 63) / 64, 256>>>(W + HIo, Wi_out, a_out, 64, W + IH2, I_N);

    // --- layer 2 aggregation (only nodes the final dot consumes) ---
    agg_k<2, true><<<(U_N + 7) / 8, 256>>>(W + UH2, W + IH2, X + OFF_A, X + LST,
                                           X + FLG_U, W + UF_, 64, U_N);
    agg_k<2, true><<<(I_N + 7) / 8, 256>>>(W + IH2, W + UH2, X + OFF_A + U_N, X + LST,
                                           X + FLG_I, W + IF_, 64, I_N);

    // --- final gather + dot ---
    final_k<<<(B_N + 7) / 8, 256>>>(userIdx, itemIdx, out);
}